// round 1
// baseline (speedup 1.0000x reference)
#include <cuda_runtime.h>

#define NB   2
#define CIN  128
#define CH   64
#define NPOS 4096
#define KSPLIT 8

// ---------------- scratch (static device globals; no allocs) ----------------
__device__ float g_q[NB * CH * NPOS];
__device__ float g_k[NB * CH * NPOS];
__device__ float g_v[NB * CH * NPOS];
__device__ float g_S[(size_t)NB * NPOS * NPOS];            // 128 MB
__device__ float g_aggp[KSPLIT][NB * CH * NPOS];           // split-K partials
__device__ float g_agg[NB * CH * NPOS];

// ---------------- K1: q/k/v = W * x ----------------
// grid (NB, NPOS/128, 24), block 128. Each thread: 1 pos, 8 out-channels.
__global__ void __launch_bounds__(128) qkv_kernel(
    const float* __restrict__ x,
    const float* __restrict__ Wq,
    const float* __restrict__ Wk,
    const float* __restrict__ Wv)
{
    int b   = blockIdx.x;
    int pos = blockIdx.y * 128 + threadIdx.x;
    int oc  = blockIdx.z * 8;           // 0..184
    int mat = oc / CH;
    int o0  = oc % CH;
    const float* W;
    float* out;
    if (mat == 0)      { W = Wq; out = g_q; }
    else if (mat == 1) { W = Wk; out = g_k; }
    else               { W = Wv; out = g_v; }

    float acc[8];
#pragma unroll
    for (int u = 0; u < 8; u++) acc[u] = 0.f;

    const float* xp = x + (size_t)b * CIN * NPOS + pos;
#pragma unroll 4
    for (int c = 0; c < CIN; c++) {
        float xv = xp[(size_t)c * NPOS];
#pragma unroll
        for (int u = 0; u < 8; u++)
            acc[u] += W[(o0 + u) * CIN + c] * xv;
    }
#pragma unroll
    for (int u = 0; u < 8; u++)
        out[((size_t)b * CH + o0 + u) * NPOS + pos] = acc[u];
}

// ---------------- K2: S[i][j] = sum_c k[c][i] * q[c][j] ----------------
// grid (32 jtiles, 32 itiles, NB), block 256, 128x128 tile, 8x8 microtile.
__global__ void __launch_bounds__(256) scores_kernel()
{
    int b  = blockIdx.z;
    int i0 = blockIdx.y * 128;
    int j0 = blockIdx.x * 128;

    __shared__ float sK[32][128];
    __shared__ float sQ[32][128];

    const float* kb = g_k + (size_t)b * CH * NPOS;
    const float* qb = g_q + (size_t)b * CH * NPOS;

    float acc[8][8];
#pragma unroll
    for (int u = 0; u < 8; u++)
#pragma unroll
        for (int v = 0; v < 8; v++) acc[u][v] = 0.f;

    int tid = threadIdx.x;
    int ty = tid >> 4, tx = tid & 15;

    for (int c0 = 0; c0 < CH; c0 += 32) {
        __syncthreads();
#pragma unroll
        for (int l = 0; l < 16; l++) {
            int idx = tid + l * 256;
            int cc = idx >> 7, col = idx & 127;
            sK[cc][col] = kb[(size_t)(c0 + cc) * NPOS + i0 + col];
            sQ[cc][col] = qb[(size_t)(c0 + cc) * NPOS + j0 + col];
        }
        __syncthreads();
#pragma unroll
        for (int cc = 0; cc < 32; cc++) {
            float a[8], bb[8];
            *(float4*)&a[0]  = *(float4*)&sK[cc][ty * 8];
            *(float4*)&a[4]  = *(float4*)&sK[cc][ty * 8 + 4];
            *(float4*)&bb[0] = *(float4*)&sQ[cc][tx * 8];
            *(float4*)&bb[4] = *(float4*)&sQ[cc][tx * 8 + 4];
#pragma unroll
            for (int u = 0; u < 8; u++)
#pragma unroll
                for (int v = 0; v < 8; v++)
                    acc[u][v] += a[u] * bb[v];
        }
    }

    float* Sb = g_S + (size_t)b * NPOS * NPOS;
#pragma unroll
    for (int u = 0; u < 8; u++) {
        size_t row = (size_t)(i0 + ty * 8 + u) * NPOS + j0 + tx * 8;
        *(float4*)&Sb[row]     = *(float4*)&acc[u][0];
        *(float4*)&Sb[row + 4] = *(float4*)&acc[u][4];
    }
}

// ---------------- K3: in-place row softmax over j ----------------
// grid (NPOS, NB), block 256; row held in registers (16/thread).
__global__ void __launch_bounds__(256) softmax_kernel()
{
    int b = blockIdx.y;
    int i = blockIdx.x;
    float* row = g_S + ((size_t)b * NPOS + i) * NPOS;
    int tid = threadIdx.x;

    float r[16];
#pragma unroll
    for (int l = 0; l < 16; l++) r[l] = row[tid + l * 256];

    // row max
    float m = -1e30f;
#pragma unroll
    for (int l = 0; l < 16; l++) m = fmaxf(m, r[l]);
#pragma unroll
    for (int o = 16; o; o >>= 1) m = fmaxf(m, __shfl_xor_sync(0xffffffffu, m, o));

    __shared__ float sred[8];
    __shared__ float sbc;
    int warp = tid >> 5, lane = tid & 31;
    if (lane == 0) sred[warp] = m;
    __syncthreads();
    if (tid < 32) {
        float mm = (tid < 8) ? sred[tid] : -1e30f;
#pragma unroll
        for (int o = 4; o; o >>= 1) mm = fmaxf(mm, __shfl_xor_sync(0xffffffffu, mm, o));
        if (tid == 0) sbc = mm;
    }
    __syncthreads();
    m = sbc;
    __syncthreads();

    // sum of exp
    float s = 0.f;
#pragma unroll
    for (int l = 0; l < 16; l++) { r[l] = __expf(r[l] - m); s += r[l]; }
#pragma unroll
    for (int o = 16; o; o >>= 1) s += __shfl_xor_sync(0xffffffffu, s, o);
    if (lane == 0) sred[warp] = s;
    __syncthreads();
    if (tid < 32) {
        float ss = (tid < 8) ? sred[tid] : 0.f;
#pragma unroll
        for (int o = 4; o; o >>= 1) ss += __shfl_xor_sync(0xffffffffu, ss, o);
        if (tid == 0) sbc = ss;
    }
    __syncthreads();
    float inv = 1.f / sbc;

#pragma unroll
    for (int l = 0; l < 16; l++) row[tid + l * 256] = r[l] * inv;
}

// ---------------- K4: agg partial, split-K (deterministic) ----------------
// agg[c][j] = sum_i v[c][i] * A[i][j].  grid (32 jtiles, KSPLIT, NB), block 256.
// tile M=64(c) x N=128(j), K-chunk 32; micro 8(c) x 4(j).
__global__ void __launch_bounds__(256) agg_kernel()
{
    int b  = blockIdx.z;
    int ks = blockIdx.y;
    int j0 = blockIdx.x * 128;
    int ibase = ks * (NPOS / KSPLIT);

    __shared__ float sV[32][65];
    __shared__ float sA[32][128];

    const float* vb = g_v + (size_t)b * CH * NPOS;
    const float* Sb = g_S + (size_t)b * NPOS * NPOS;

    float acc[8][4];
#pragma unroll
    for (int u = 0; u < 8; u++)
#pragma unroll
        for (int v = 0; v < 4; v++) acc[u][v] = 0.f;

    int tid = threadIdx.x;
    int tx = tid & 31, ty = tid >> 5;

    for (int ic = 0; ic < NPOS / KSPLIT; ic += 32) {
        int i0 = ibase + ic;
        __syncthreads();
#pragma unroll
        for (int l = 0; l < 8; l++) {
            int idx = tid + l * 256;
            int c = idx >> 5, ii = idx & 31;
            sV[ii][c] = vb[(size_t)c * NPOS + i0 + ii];
        }
#pragma unroll
        for (int l = 0; l < 16; l++) {
            int idx = tid + l * 256;
            int ii = idx >> 7, jj = idx & 127;
            sA[ii][jj] = Sb[(size_t)(i0 + ii) * NPOS + j0 + jj];
        }
        __syncthreads();
#pragma unroll
        for (int ii = 0; ii < 32; ii++) {
            float a[8], bb[4];
#pragma unroll
            for (int u = 0; u < 8; u++) a[u] = sV[ii][ty * 8 + u];
            *(float4*)&bb[0] = *(float4*)&sA[ii][tx * 4];
#pragma unroll
            for (int u = 0; u < 8; u++)
#pragma unroll
                for (int v = 0; v < 4; v++)
                    acc[u][v] += a[u] * bb[v];
        }
    }

    float* ap = g_aggp[ks] + (size_t)b * CH * NPOS;
#pragma unroll
    for (int u = 0; u < 8; u++)
        *(float4*)&ap[(size_t)(ty * 8 + u) * NPOS + j0 + tx * 4] = *(float4*)&acc[u][0];
}

// ---------------- K4b: reduce split-K partials ----------------
__global__ void __launch_bounds__(256) agg_reduce_kernel()
{
    int e = blockIdx.x * 256 + threadIdx.x;
    if (e >= NB * CH * NPOS) return;
    float s = 0.f;
#pragma unroll
    for (int ks = 0; ks < KSPLIT; ks++) s += g_aggp[ks][e];
    g_agg[e] = s;
}

// ---------------- K5: out = Wpost * agg + x ----------------
// grid (NB, NPOS/128, 16), block 128; thread: 1 pos, 8 out-channels.
__global__ void __launch_bounds__(128) post_kernel(
    const float* __restrict__ x,
    const float* __restrict__ Wpost,
    float* __restrict__ out)
{
    int b   = blockIdx.x;
    int pos = blockIdx.y * 128 + threadIdx.x;
    int o0  = blockIdx.z * 8;

    float acc[8];
#pragma unroll
    for (int u = 0; u < 8; u++) acc[u] = 0.f;

    const float* ap = g_agg + (size_t)b * CH * NPOS + pos;
#pragma unroll 4
    for (int c = 0; c < CH; c++) {
        float av = ap[(size_t)c * NPOS];
#pragma unroll
        for (int u = 0; u < 8; u++)
            acc[u] += Wpost[(o0 + u) * CH + c] * av;
    }
#pragma unroll
    for (int u = 0; u < 8; u++) {
        size_t o = ((size_t)b * CIN + o0 + u) * NPOS + pos;
        out[o] = acc[u] + x[o];
    }
}

// ---------------- launch ----------------
extern "C" void kernel_launch(void* const* d_in, const int* in_sizes, int n_in,
                              void* d_out, int out_size)
{
    const float* x     = (const float*)d_in[0];
    const float* Wq    = (const float*)d_in[1];
    const float* Wk    = (const float*)d_in[2];
    const float* Wv    = (const float*)d_in[3];
    const float* Wpost = (const float*)d_in[4];
    float* out = (float*)d_out;

    qkv_kernel<<<dim3(NB, NPOS / 128, 24), 128>>>(x, Wq, Wk, Wv);
    scores_kernel<<<dim3(NPOS / 128, NPOS / 128, NB), 256>>>();
    softmax_kernel<<<dim3(NPOS, NB), 256>>>();
    agg_kernel<<<dim3(NPOS / 128, KSPLIT, NB), 256>>>();
    agg_reduce_kernel<<<(NB * CH * NPOS + 255) / 256, 256>>>();
    post_kernel<<<dim3(NB, NPOS / 128, 16), 128>>>(x, Wpost, out);
}

// round 2
// speedup vs baseline: 1.0811x; 1.0811x over previous
#include <cuda_runtime.h>

#define NB   2
#define CIN  128
#define CH   64
#define NPOS 4096
#define JB   32            // number of 128-wide j blocks in scores
#define ASPLIT 16          // split-K over i in agg

// ---------------- scratch (static device globals; no allocs) ----------------
__device__ float g_q[NB * CH * NPOS];
__device__ float g_k[NB * CH * NPOS];
__device__ float g_v[NB * CH * NPOS];
__device__ float g_S[(size_t)NB * NPOS * NPOS];          // 128 MB raw scores
__device__ float g_mpart[NB * JB * NPOS];                // partial row max per j-block
__device__ float g_spart[NB * JB * NPOS];                // partial sum-exp per j-block
__device__ float g_m[NB * NPOS];                         // row max
__device__ float g_w[NB * NPOS];                         // 1/row-sum
__device__ float g_aggp[ASPLIT][NB * CH * NPOS];         // split-K partials (32MB)
__device__ float g_agg[NB * CH * NPOS];

// ---------------- K1: q/k/v = W * x ----------------
__global__ void __launch_bounds__(128) qkv_kernel(
    const float* __restrict__ x,
    const float* __restrict__ Wq,
    const float* __restrict__ Wk,
    const float* __restrict__ Wv)
{
    int b   = blockIdx.x;
    int pos = blockIdx.y * 128 + threadIdx.x;
    int oc  = blockIdx.z * 8;
    int mat = oc / CH;
    int o0  = oc % CH;
    const float* W;
    float* out;
    if (mat == 0)      { W = Wq; out = g_q; }
    else if (mat == 1) { W = Wk; out = g_k; }
    else               { W = Wv; out = g_v; }

    float acc[8];
#pragma unroll
    for (int u = 0; u < 8; u++) acc[u] = 0.f;

    const float* xp = x + (size_t)b * CIN * NPOS + pos;
#pragma unroll 4
    for (int c = 0; c < CIN; c++) {
        float xv = xp[(size_t)c * NPOS];
#pragma unroll
        for (int u = 0; u < 8; u++)
            acc[u] += W[(o0 + u) * CIN + c] * xv;
    }
#pragma unroll
    for (int u = 0; u < 8; u++)
        out[((size_t)b * CH + o0 + u) * NPOS + pos] = acc[u];
}

// ---------------- K2: S tile + partial softmax stats in epilogue ----------------
// grid (32 jt, 32 it, NB), block 256. Tile 128x128, micro 8x8 split (4+4).
// rows: {i0 + ty*4+u, i0+64+ty*4+u}, cols: {j0 + tx*4+v, j0+64+tx*4+v}
__global__ void __launch_bounds__(256, 2) scores_kernel()
{
    int b  = blockIdx.z;
    int i0 = blockIdx.y * 128;
    int j0 = blockIdx.x * 128;
    int jb = blockIdx.x;

    __shared__ float sK[32][128];
    __shared__ float sQ[32][128];

    const float* kb = g_k + (size_t)b * CH * NPOS;
    const float* qb = g_q + (size_t)b * CH * NPOS;

    float acc[8][8];
#pragma unroll
    for (int u = 0; u < 8; u++)
#pragma unroll
        for (int v = 0; v < 8; v++) acc[u][v] = 0.f;

    int tid = threadIdx.x;
    int ty = tid >> 4, tx = tid & 15;

    for (int c0 = 0; c0 < CH; c0 += 32) {
        __syncthreads();
#pragma unroll
        for (int l = 0; l < 16; l++) {
            int idx = tid + l * 256;
            int cc = idx >> 7, col = idx & 127;
            sK[cc][col] = kb[(size_t)(c0 + cc) * NPOS + i0 + col];
            sQ[cc][col] = qb[(size_t)(c0 + cc) * NPOS + j0 + col];
        }
        __syncthreads();
#pragma unroll 8
        for (int cc = 0; cc < 32; cc++) {
            float a[8], bb[8];
            *(float4*)&a[0]  = *(float4*)&sK[cc][ty * 4];
            *(float4*)&a[4]  = *(float4*)&sK[cc][64 + ty * 4];
            *(float4*)&bb[0] = *(float4*)&sQ[cc][tx * 4];
            *(float4*)&bb[4] = *(float4*)&sQ[cc][64 + tx * 4];
#pragma unroll
            for (int u = 0; u < 8; u++)
#pragma unroll
                for (int v = 0; v < 8; v++)
                    acc[u][v] += a[u] * bb[v];
        }
    }

    // ---- write raw S tile ----
    float* Sb = g_S + (size_t)b * NPOS * NPOS;
#pragma unroll
    for (int u = 0; u < 8; u++) {
        int row = i0 + ((u < 4) ? (ty * 4 + u) : (64 + ty * 4 + u - 4));
        size_t base = (size_t)row * NPOS + j0;
        *(float4*)&Sb[base + tx * 4]      = *(float4*)&acc[u][0];
        *(float4*)&Sb[base + 64 + tx * 4] = *(float4*)&acc[u][4];
    }

    // ---- partial softmax stats: per row, over this block's 128 cols ----
    // Each row lives across the 16 tx lanes of one ty group.
#pragma unroll
    for (int u = 0; u < 8; u++) {
        float rm = acc[u][0];
#pragma unroll
        for (int v = 1; v < 8; v++) rm = fmaxf(rm, acc[u][v]);
#pragma unroll
        for (int o = 8; o; o >>= 1) rm = fmaxf(rm, __shfl_xor_sync(0xffffffffu, rm, o));
        float rs = 0.f;
#pragma unroll
        for (int v = 0; v < 8; v++) rs += __expf(acc[u][v] - rm);
#pragma unroll
        for (int o = 8; o; o >>= 1) rs += __shfl_xor_sync(0xffffffffu, rs, o);
        if (tx == 0) {
            int row = i0 + ((u < 4) ? (ty * 4 + u) : (64 + ty * 4 + u - 4));
            g_mpart[((size_t)b * JB + jb) * NPOS + row] = rm;
            g_spart[((size_t)b * JB + jb) * NPOS + row] = rs;
        }
    }
}

// ---------------- K3: combine partial stats -> m_i, w_i ----------------
__global__ void __launch_bounds__(256) combine_kernel()
{
    int e = blockIdx.x * 256 + threadIdx.x;      // e = b*NPOS + i
    if (e >= NB * NPOS) return;
    int b = e / NPOS, i = e % NPOS;
    const float* mp = g_mpart + (size_t)b * JB * NPOS + i;
    const float* sp = g_spart + (size_t)b * JB * NPOS + i;
    float m = -1e30f;
#pragma unroll
    for (int jb = 0; jb < JB; jb++) m = fmaxf(m, mp[(size_t)jb * NPOS]);
    float s = 0.f;
#pragma unroll
    for (int jb = 0; jb < JB; jb++)
        s += __expf(mp[(size_t)jb * NPOS] - m) * sp[(size_t)jb * NPOS];
    g_m[e] = m;
    g_w[e] = 1.f / s;
}

// ---------------- K4: agg partial with inline softmax ----------------
// agg[c][j] = sum_i v[c][i] * exp(S[i][j]-m_i)*w_i
// grid (16 jt, ASPLIT, NB), block 256. Tile c=64 x j=256, K-chunk 32.
// micro: c {ty*4+u, 32+ty*4+u}, j {tx*4+v, 128+tx*4+v}; ty=tid>>5, tx=tid&31.
__global__ void __launch_bounds__(256, 2) agg_kernel()
{
    int b  = blockIdx.z;
    int ks = blockIdx.y;
    int j0 = blockIdx.x * 256;
    const int IRANGE = NPOS / ASPLIT;            // 256
    int ibase = ks * IRANGE;

    __shared__ float sV[CH][33];                 // [c][ii] transposed
    __shared__ float sP[32][256];
    __shared__ float sM[32], sW[32];

    const float* vb = g_v + (size_t)b * CH * NPOS;
    const float* Sb = g_S + (size_t)b * NPOS * NPOS;

    float acc[8][8];
#pragma unroll
    for (int u = 0; u < 8; u++)
#pragma unroll
        for (int v = 0; v < 8; v++) acc[u][v] = 0.f;

    int tid = threadIdx.x;
    int ty = tid >> 5, tx = tid & 31;

    for (int ic = 0; ic < IRANGE; ic += 32) {
        int i0 = ibase + ic;
        __syncthreads();
        if (tid < 32) {
            sM[tid] = g_m[b * NPOS + i0 + tid];
            sW[tid] = g_w[b * NPOS + i0 + tid];
        }
        // V: 32 i x 64 c -> sV[c][ii]; consecutive tid read consecutive i
#pragma unroll
        for (int l = 0; l < 8; l++) {
            int idx = tid + l * 256;
            int c = idx >> 5, ii = idx & 31;
            sV[c][ii] = vb[(size_t)c * NPOS + i0 + ii];
        }
        __syncthreads();   // sM/sW ready before exp below uses them? (exp uses sM in this pass)
        // P tile: apply exp inline while staging
#pragma unroll
        for (int l = 0; l < 32; l++) {
            int idx = tid + l * 256;
            int ii = idx >> 8, jj = idx & 255;
            float sval = Sb[(size_t)(i0 + ii) * NPOS + j0 + jj];
            sP[ii][jj] = __expf(sval - sM[ii]) * sW[ii];
        }
        __syncthreads();
#pragma unroll 8
        for (int ii = 0; ii < 32; ii++) {
            float a[8], bb[8];
#pragma unroll
            for (int u = 0; u < 4; u++) {
                a[u]     = sV[ty * 4 + u][ii];
                a[4 + u] = sV[32 + ty * 4 + u][ii];
            }
            *(float4*)&bb[0] = *(float4*)&sP[ii][tx * 4];
            *(float4*)&bb[4] = *(float4*)&sP[ii][128 + tx * 4];
#pragma unroll
            for (int u = 0; u < 8; u++)
#pragma unroll
                for (int v = 0; v < 8; v++)
                    acc[u][v] += a[u] * bb[v];
        }
    }

    float* ap = g_aggp[ks] + (size_t)b * CH * NPOS;
#pragma unroll
    for (int u = 0; u < 8; u++) {
        int c = (u < 4) ? (ty * 4 + u) : (32 + ty * 4 + u - 4);
        size_t base = (size_t)c * NPOS + j0;
        *(float4*)&ap[base + tx * 4]       = *(float4*)&acc[u][0];
        *(float4*)&ap[base + 128 + tx * 4] = *(float4*)&acc[u][4];
    }
}

// ---------------- K4b: reduce split-K partials ----------------
__global__ void __launch_bounds__(256) agg_reduce_kernel()
{
    int e = blockIdx.x * 256 + threadIdx.x;
    if (e >= NB * CH * NPOS) return;
    float s = 0.f;
#pragma unroll
    for (int ks = 0; ks < ASPLIT; ks++) s += g_aggp[ks][e];
    g_agg[e] = s;
}

// ---------------- K5: out = Wpost * agg + x ----------------
__global__ void __launch_bounds__(128) post_kernel(
    const float* __restrict__ x,
    const float* __restrict__ Wpost,
    float* __restrict__ out)
{
    int b   = blockIdx.x;
    int pos = blockIdx.y * 128 + threadIdx.x;
    int o0  = blockIdx.z * 8;

    float acc[8];
#pragma unroll
    for (int u = 0; u < 8; u++) acc[u] = 0.f;

    const float* ap = g_agg + (size_t)b * CH * NPOS + pos;
#pragma unroll 4
    for (int c = 0; c < CH; c++) {
        float av = ap[(size_t)c * NPOS];
#pragma unroll
        for (int u = 0; u < 8; u++)
            acc[u] += Wpost[(o0 + u) * CH + c] * av;
    }
#pragma unroll
    for (int u = 0; u < 8; u++) {
        size_t o = ((size_t)b * CIN + o0 + u) * NPOS + pos;
        out[o] = acc[u] + x[o];
    }
}

// ---------------- launch ----------------
extern "C" void kernel_launch(void* const* d_in, const int* in_sizes, int n_in,
                              void* d_out, int out_size)
{
    const float* x     = (const float*)d_in[0];
    const float* Wq    = (const float*)d_in[1];
    const float* Wk    = (const float*)d_in[2];
    const float* Wv    = (const float*)d_in[3];
    const float* Wpost = (const float*)d_in[4];
    float* out = (float*)d_out;

    qkv_kernel<<<dim3(NB, NPOS / 128, 24), 128>>>(x, Wq, Wk, Wv);
    scores_kernel<<<dim3(NPOS / 128, NPOS / 128, NB), 256>>>();
    combine_kernel<<<(NB * NPOS + 255) / 256, 256>>>();
    agg_kernel<<<dim3(NPOS / 256, ASPLIT, NB), 256>>>();
    agg_reduce_kernel<<<(NB * CH * NPOS + 255) / 256, 256>>>();
    post_kernel<<<dim3(NB, NPOS / 128, 16), 128>>>(x, Wpost, out);
}

// round 3
// speedup vs baseline: 1.1124x; 1.0290x over previous
#include <cuda_runtime.h>

#define NB   2
#define CIN  128
#define CH   64
#define NPOS 4096
#define JB   32            // number of 128-wide j blocks in scores
#define ASPLIT 16          // split-K over i in agg

typedef unsigned long long u64;

// ---------------- packed f32x2 helpers ----------------
__device__ __forceinline__ void ffma2(u64& d, u64 a, u64 b) {
    asm("fma.rn.f32x2 %0, %1, %2, %0;" : "+l"(d) : "l"(a), "l"(b));
}
__device__ __forceinline__ u64 pack2(float x, float y) {
    u64 r; asm("mov.b64 %0, {%1, %2};" : "=l"(r) : "f"(x), "f"(y)); return r;
}
__device__ __forceinline__ void unpack2(u64 p, float& x, float& y) {
    asm("mov.b64 {%0, %1}, %2;" : "=f"(x), "=f"(y) : "l"(p));
}

// ---------------- scratch (static device globals; no allocs) ----------------
__device__ float g_q[NB * CH * NPOS];
__device__ float g_k[NB * CH * NPOS];
__device__ float g_v[NB * CH * NPOS];
__device__ float g_S[(size_t)NB * NPOS * NPOS];          // 128 MB raw scores
__device__ float g_mpart[NB * JB * NPOS];
__device__ float g_spart[NB * JB * NPOS];
__device__ float g_m[NB * NPOS];
__device__ float g_w[NB * NPOS];
__device__ float g_aggp[ASPLIT][NB * CH * NPOS];
__device__ float g_agg[NB * CH * NPOS];

// ---------------- K1: q/k/v = W * x ----------------
__global__ void __launch_bounds__(128) qkv_kernel(
    const float* __restrict__ x,
    const float* __restrict__ Wq,
    const float* __restrict__ Wk,
    const float* __restrict__ Wv)
{
    int b   = blockIdx.x;
    int pos = blockIdx.y * 128 + threadIdx.x;
    int oc  = blockIdx.z * 8;
    int mat = oc / CH;
    int o0  = oc % CH;
    const float* W;
    float* out;
    if (mat == 0)      { W = Wq; out = g_q; }
    else if (mat == 1) { W = Wk; out = g_k; }
    else               { W = Wv; out = g_v; }

    float acc[8];
#pragma unroll
    for (int u = 0; u < 8; u++) acc[u] = 0.f;

    const float* xp = x + (size_t)b * CIN * NPOS + pos;
#pragma unroll 4
    for (int c = 0; c < CIN; c++) {
        float xv = xp[(size_t)c * NPOS];
#pragma unroll
        for (int u = 0; u < 8; u++)
            acc[u] += W[(o0 + u) * CIN + c] * xv;
    }
#pragma unroll
    for (int u = 0; u < 8; u++)
        out[((size_t)b * CH + o0 + u) * NPOS + pos] = acc[u];
}

// ---------------- K2: S tile + partial softmax stats, FFMA2 ----------------
// grid (32 jt, 32 it, NB), block 256. Tile 128x128, micro 8x8 split (4+4).
__global__ void __launch_bounds__(256, 2) scores_kernel()
{
    int b  = blockIdx.z;
    int i0 = blockIdx.y * 128;
    int j0 = blockIdx.x * 128;
    int jb = blockIdx.x;

    __shared__ float sK[32][128];
    __shared__ float sQ[32][128];

    const float* kb = g_k + (size_t)b * CH * NPOS;
    const float* qb = g_q + (size_t)b * CH * NPOS;

    u64 acc[8][4];
#pragma unroll
    for (int u = 0; u < 8; u++)
#pragma unroll
        for (int v = 0; v < 4; v++) acc[u][v] = pack2(0.f, 0.f);

    int tid = threadIdx.x;
    int ty = tid >> 4, tx = tid & 15;

    for (int c0 = 0; c0 < CH; c0 += 32) {
        __syncthreads();
#pragma unroll
        for (int l = 0; l < 16; l++) {
            int idx = tid + l * 256;
            int cc = idx >> 7, col = idx & 127;
            sK[cc][col] = kb[(size_t)(c0 + cc) * NPOS + i0 + col];
            sQ[cc][col] = qb[(size_t)(c0 + cc) * NPOS + j0 + col];
        }
        __syncthreads();
#pragma unroll 8
        for (int cc = 0; cc < 32; cc++) {
            float a[8];
            float4 b0 = *(float4*)&sQ[cc][tx * 4];
            float4 b1 = *(float4*)&sQ[cc][64 + tx * 4];
            *(float4*)&a[0] = *(float4*)&sK[cc][ty * 4];
            *(float4*)&a[4] = *(float4*)&sK[cc][64 + ty * 4];
            u64 bp[4];
            bp[0] = pack2(b0.x, b0.y);
            bp[1] = pack2(b0.z, b0.w);
            bp[2] = pack2(b1.x, b1.y);
            bp[3] = pack2(b1.z, b1.w);
#pragma unroll
            for (int u = 0; u < 8; u++) {
                u64 ap = pack2(a[u], a[u]);
#pragma unroll
                for (int v = 0; v < 4; v++)
                    ffma2(acc[u][v], ap, bp[v]);
            }
        }
    }

    // ---- write raw S tile (pairs are contiguous j) ----
    float* Sb = g_S + (size_t)b * NPOS * NPOS;
#pragma unroll
    for (int u = 0; u < 8; u++) {
        int row = i0 + ((u < 4) ? (ty * 4 + u) : (64 + ty * 4 + u - 4));
        size_t base = (size_t)row * NPOS + j0;
        ulonglong2 s0; s0.x = acc[u][0]; s0.y = acc[u][1];
        ulonglong2 s1; s1.x = acc[u][2]; s1.y = acc[u][3];
        *(ulonglong2*)&Sb[base + tx * 4]      = s0;
        *(ulonglong2*)&Sb[base + 64 + tx * 4] = s1;
    }

    // ---- partial softmax stats per row over this block's 128 cols ----
#pragma unroll
    for (int u = 0; u < 8; u++) {
        float f[8];
#pragma unroll
        for (int v = 0; v < 4; v++) unpack2(acc[u][v], f[2 * v], f[2 * v + 1]);
        float rm = f[0];
#pragma unroll
        for (int v = 1; v < 8; v++) rm = fmaxf(rm, f[v]);
#pragma unroll
        for (int o = 8; o; o >>= 1) rm = fmaxf(rm, __shfl_xor_sync(0xffffffffu, rm, o));
        float rs = 0.f;
#pragma unroll
        for (int v = 0; v < 8; v++) rs += __expf(f[v] - rm);
#pragma unroll
        for (int o = 8; o; o >>= 1) rs += __shfl_xor_sync(0xffffffffu, rs, o);
        if (tx == 0) {
            int row = i0 + ((u < 4) ? (ty * 4 + u) : (64 + ty * 4 + u - 4));
            g_mpart[((size_t)b * JB + jb) * NPOS + row] = rm;
            g_spart[((size_t)b * JB + jb) * NPOS + row] = rs;
        }
    }
}

// ---------------- K3: combine partial stats -> m_i, w_i ----------------
__global__ void __launch_bounds__(256) combine_kernel()
{
    int e = blockIdx.x * 256 + threadIdx.x;
    if (e >= NB * NPOS) return;
    int b = e / NPOS, i = e % NPOS;
    const float* mp = g_mpart + (size_t)b * JB * NPOS + i;
    const float* sp = g_spart + (size_t)b * JB * NPOS + i;
    float m = -1e30f;
#pragma unroll
    for (int jb = 0; jb < JB; jb++) m = fmaxf(m, mp[(size_t)jb * NPOS]);
    float s = 0.f;
#pragma unroll
    for (int jb = 0; jb < JB; jb++)
        s += __expf(mp[(size_t)jb * NPOS] - m) * sp[(size_t)jb * NPOS];
    g_m[e] = m;
    g_w[e] = 1.f / s;
}

// ---------------- K4: agg partial with inline softmax, FFMA2 ----------------
// agg[c][j] = sum_i v[c][i] * exp(S[i][j]-m_i)*w_i
// grid (16 jt, ASPLIT, NB), block 256. Tile c=64 x j=256, K-chunk 32.
__global__ void __launch_bounds__(256, 2) agg_kernel()
{
    int b  = blockIdx.z;
    int ks = blockIdx.y;
    int j0 = blockIdx.x * 256;
    const int IRANGE = NPOS / ASPLIT;            // 256
    int ibase = ks * IRANGE;

    __shared__ float sV[CH][33];
    __shared__ float sP[32][256];
    __shared__ float sM[32], sW[32];

    const float* vb = g_v + (size_t)b * CH * NPOS;
    const float* Sb = g_S + (size_t)b * NPOS * NPOS;

    u64 acc[8][4];
#pragma unroll
    for (int u = 0; u < 8; u++)
#pragma unroll
        for (int v = 0; v < 4; v++) acc[u][v] = pack2(0.f, 0.f);

    int tid = threadIdx.x;
    int ty = tid >> 5, tx = tid & 31;

    for (int ic = 0; ic < IRANGE; ic += 32) {
        int i0 = ibase + ic;
        __syncthreads();
        if (tid < 32) {
            sM[tid] = g_m[b * NPOS + i0 + tid];
            sW[tid] = g_w[b * NPOS + i0 + tid];
        }
#pragma unroll
        for (int l = 0; l < 8; l++) {
            int idx = tid + l * 256;
            int c = idx >> 5, ii = idx & 31;
            sV[c][ii] = vb[(size_t)c * NPOS + i0 + ii];
        }
        __syncthreads();
#pragma unroll
        for (int l = 0; l < 32; l++) {
            int idx = tid + l * 256;
            int ii = idx >> 8, jj = idx & 255;
            float sval = Sb[(size_t)(i0 + ii) * NPOS + j0 + jj];
            sP[ii][jj] = __expf(sval - sM[ii]) * sW[ii];
        }
        __syncthreads();
#pragma unroll 8
        for (int ii = 0; ii < 32; ii++) {
            float a[8];
            float4 b0 = *(float4*)&sP[ii][tx * 4];
            float4 b1 = *(float4*)&sP[ii][128 + tx * 4];
#pragma unroll
            for (int u = 0; u < 4; u++) {
                a[u]     = sV[ty * 4 + u][ii];
                a[4 + u] = sV[32 + ty * 4 + u][ii];
            }
            u64 bp[4];
            bp[0] = pack2(b0.x, b0.y);
            bp[1] = pack2(b0.z, b0.w);
            bp[2] = pack2(b1.x, b1.y);
            bp[3] = pack2(b1.z, b1.w);
#pragma unroll
            for (int u = 0; u < 8; u++) {
                u64 ap = pack2(a[u], a[u]);
#pragma unroll
                for (int v = 0; v < 4; v++)
                    ffma2(acc[u][v], ap, bp[v]);
            }
        }
    }

    float* ap_out = g_aggp[ks] + (size_t)b * CH * NPOS;
#pragma unroll
    for (int u = 0; u < 8; u++) {
        int c = (u < 4) ? (ty * 4 + u) : (32 + ty * 4 + u - 4);
        size_t base = (size_t)c * NPOS + j0;
        ulonglong2 s0; s0.x = acc[u][0]; s0.y = acc[u][1];
        ulonglong2 s1; s1.x = acc[u][2]; s1.y = acc[u][3];
        *(ulonglong2*)&ap_out[base + tx * 4]       = s0;
        *(ulonglong2*)&ap_out[base + 128 + tx * 4] = s1;
    }
}

// ---------------- K4b: reduce split-K partials ----------------
__global__ void __launch_bounds__(256) agg_reduce_kernel()
{
    int e = blockIdx.x * 256 + threadIdx.x;
    if (e >= NB * CH * NPOS) return;
    float s = 0.f;
#pragma unroll
    for (int ks = 0; ks < ASPLIT; ks++) s += g_aggp[ks][e];
    g_agg[e] = s;
}

// ---------------- K5: out = Wpost * agg + x ----------------
__global__ void __launch_bounds__(128) post_kernel(
    const float* __restrict__ x,
    const float* __restrict__ Wpost,
    float* __restrict__ out)
{
    int b   = blockIdx.x;
    int pos = blockIdx.y * 128 + threadIdx.x;
    int o0  = blockIdx.z * 8;

    float acc[8];
#pragma unroll
    for (int u = 0; u < 8; u++) acc[u] = 0.f;

    const float* ap = g_agg + (size_t)b * CH * NPOS + pos;
#pragma unroll 4
    for (int c = 0; c < CH; c++) {
        float av = ap[(size_t)c * NPOS];
#pragma unroll
        for (int u = 0; u < 8; u++)
            acc[u] += Wpost[(o0 + u) * CH + c] * av;
    }
#pragma unroll
    for (int u = 0; u < 8; u++) {
        size_t o = ((size_t)b * CIN + o0 + u) * NPOS + pos;
        out[o] = acc[u] + x[o];
    }
}

// ---------------- launch ----------------
extern "C" void kernel_launch(void* const* d_in, const int* in_sizes, int n_in,
                              void* d_out, int out_size)
{
    const float* x     = (const float*)d_in[0];
    const float* Wq    = (const float*)d_in[1];
    const float* Wk    = (const float*)d_in[2];
    const float* Wv    = (const float*)d_in[3];
    const float* Wpost = (const float*)d_in[4];
    float* out = (float*)d_out;

    qkv_kernel<<<dim3(NB, NPOS / 128, 24), 128>>>(x, Wq, Wk, Wv);
    scores_kernel<<<dim3(NPOS / 128, NPOS / 128, NB), 256>>>();
    combine_kernel<<<(NB * NPOS + 255) / 256, 256>>>();
    agg_kernel<<<dim3(NPOS / 256, ASPLIT, NB), 256>>>();
    agg_reduce_kernel<<<(NB * CH * NPOS + 255) / 256, 256>>>();
    post_kernel<<<dim3(NB, NPOS / 128, 16), 128>>>(x, Wpost, out);
}

// round 6
// speedup vs baseline: 1.3033x; 1.1716x over previous
#include <cuda_runtime.h>
#include <cstdint>

#define NB   2
#define CIN  128
#define CH   64
#define NPOS 4096
#define JB   128          // 32-wide stat blocks
#define ASPLIT 8

typedef uint32_t u32;

// ================= helpers =================
__device__ __forceinline__ float to_tf32(float x) {
    float r; asm("cvt.rna.tf32.f32 %0, %1;" : "=f"(r) : "f"(x)); return r;
}
__device__ __forceinline__ void mma_tf32(float c[4], u32 a0, u32 a1, u32 a2, u32 a3,
                                         u32 b0, u32 b1) {
    asm volatile("mma.sync.aligned.m16n8k8.row.col.f32.tf32.tf32.f32 "
                 "{%0,%1,%2,%3}, {%4,%5,%6,%7}, {%8,%9}, {%0,%1,%2,%3};"
                 : "+f"(c[0]), "+f"(c[1]), "+f"(c[2]), "+f"(c[3])
                 : "r"(a0), "r"(a1), "r"(a2), "r"(a3), "r"(b0), "r"(b1));
}
__device__ __forceinline__ void split32(float x, u32& hi, u32& lo) {
    float h = to_tf32(x);
    hi = __float_as_uint(h);
    lo = __float_as_uint(x - h);
}

// ================= scratch =================
__device__ float g_kT[NB * NPOS * CH];      // [b][i][c]
__device__ float g_qT[NB * NPOS * CH];      // [b][j][c]
__device__ float g_v [NB * CH * NPOS];      // [b][c][i]
__device__ float g_S [(size_t)NB * NPOS * NPOS];
__device__ float g_mpart[NB * JB * NPOS];
__device__ float g_spart[NB * JB * NPOS];
__device__ float g_m[NB * NPOS];
__device__ float g_w[NB * NPOS];
__device__ float g_aggp[ASPLIT][NB * CH * NPOS];
__device__ float g_agg[NB * CH * NPOS];

// ================= K1: qkv =================
__global__ void __launch_bounds__(128) qkv_kernel(
    const float* __restrict__ x,
    const float* __restrict__ Wq,
    const float* __restrict__ Wk,
    const float* __restrict__ Wv)
{
    int b   = blockIdx.x;
    int pos = blockIdx.y * 128 + threadIdx.x;
    int z   = blockIdx.z;            // 0..23
    int mat = z >> 3;
    int o0  = (z & 7) * 8;
    const float* W = (mat == 0) ? Wq : (mat == 1) ? Wk : Wv;

    float acc[8];
#pragma unroll
    for (int u = 0; u < 8; u++) acc[u] = 0.f;
    const float* xp = x + (size_t)b * CIN * NPOS + pos;
#pragma unroll 4
    for (int c = 0; c < CIN; c++) {
        float xv = xp[(size_t)c * NPOS];
#pragma unroll
        for (int u = 0; u < 8; u++)
            acc[u] += W[(o0 + u) * CIN + c] * xv;
    }
    if (mat == 2) {
#pragma unroll
        for (int u = 0; u < 8; u++)
            g_v[((size_t)b * CH + o0 + u) * NPOS + pos] = acc[u];
    } else {
        float* dst = (mat == 0) ? g_qT : g_kT;
        size_t base = ((size_t)b * NPOS + pos) * CH + o0;
        *(float4*)&dst[base]     = make_float4(acc[0], acc[1], acc[2], acc[3]);
        *(float4*)&dst[base + 4] = make_float4(acc[4], acc[5], acc[6], acc[7]);
    }
}

// ================= K2: scores via mma.sync tf32 (3x split) =================
// grid (32 jt, 32 it, NB), block 256 (8 warps: 2 i x 4 j).
#define SC_STRIDE 68
#define SC_SMEM (2 * 128 * SC_STRIDE * 4)
__global__ void __launch_bounds__(256) scores_kernel()
{
    extern __shared__ float sm[];
    float* sK = sm;                        // [128 i][68]
    float* sQ = sm + 128 * SC_STRIDE;      // [128 j][68]

    int b  = blockIdx.z;
    int i0 = blockIdx.y * 128;
    int j0 = blockIdx.x * 128;
    int tid = threadIdx.x, wid = tid >> 5, lane = tid & 31;
    int gid = lane >> 2, ctid = lane & 3;
    int warp_i = wid >> 2;                 // 0..1
    int warp_j = wid & 3;                  // 0..3
    int ibase = warp_i * 64, jbase = warp_j * 32;

    // stage kT/qT tiles (128 rows x 64 c), float4 coalesced
    {
        const float4* kg = (const float4*)(g_kT + ((size_t)b * NPOS + i0) * CH);
        const float4* qg = (const float4*)(g_qT + ((size_t)b * NPOS + j0) * CH);
        for (int idx = tid; idx < 2048; idx += 256) {
            int row = idx >> 4, c4 = (idx & 15) * 4;
            *(float4*)&sK[row * SC_STRIDE + c4] = kg[idx];
            *(float4*)&sQ[row * SC_STRIDE + c4] = qg[idx];
        }
    }
    __syncthreads();

    float cfr[4][4][4];
#pragma unroll
    for (int ti = 0; ti < 4; ti++)
#pragma unroll
        for (int tj = 0; tj < 4; tj++)
#pragma unroll
            for (int r = 0; r < 4; r++) cfr[ti][tj][r] = 0.f;

#pragma unroll
    for (int ks = 0; ks < 8; ks++) {
        int k = ks * 8 + ctid;
        u32 ahi[4][4], alo[4][4];
#pragma unroll
        for (int ti = 0; ti < 4; ti++) {
            const float* base0 = &sK[(ibase + ti * 16 + gid) * SC_STRIDE + k];
            const float* base1 = &sK[(ibase + ti * 16 + gid + 8) * SC_STRIDE + k];
            split32(base0[0], ahi[ti][0], alo[ti][0]);
            split32(base1[0], ahi[ti][1], alo[ti][1]);
            split32(base0[4], ahi[ti][2], alo[ti][2]);
            split32(base1[4], ahi[ti][3], alo[ti][3]);
        }
        u32 bhi[4][2], blo[4][2];
#pragma unroll
        for (int tj = 0; tj < 4; tj++) {
            const float* qb = &sQ[(jbase + tj * 8 + gid) * SC_STRIDE + k];
            split32(qb[0], bhi[tj][0], blo[tj][0]);
            split32(qb[4], bhi[tj][1], blo[tj][1]);
        }
#pragma unroll
        for (int ti = 0; ti < 4; ti++)
#pragma unroll
            for (int tj = 0; tj < 4; tj++) {
                mma_tf32(cfr[ti][tj], ahi[ti][0], ahi[ti][1], ahi[ti][2], ahi[ti][3],
                         bhi[tj][0], bhi[tj][1]);
                mma_tf32(cfr[ti][tj], ahi[ti][0], ahi[ti][1], ahi[ti][2], ahi[ti][3],
                         blo[tj][0], blo[tj][1]);
                mma_tf32(cfr[ti][tj], alo[ti][0], alo[ti][1], alo[ti][2], alo[ti][3],
                         bhi[tj][0], bhi[tj][1]);
            }
    }

    // ---- write S (float2, sector-coalesced) ----
    float* Sb = g_S + (size_t)b * NPOS * NPOS;
#pragma unroll
    for (int ti = 0; ti < 4; ti++) {
        int row0 = i0 + ibase + ti * 16 + gid;
#pragma unroll
        for (int tj = 0; tj < 4; tj++) {
            int col = j0 + jbase + tj * 8 + 2 * ctid;
            *(float2*)&Sb[(size_t)row0 * NPOS + col] =
                make_float2(cfr[ti][tj][0], cfr[ti][tj][1]);
            *(float2*)&Sb[(size_t)(row0 + 8) * NPOS + col] =
                make_float2(cfr[ti][tj][2], cfr[ti][tj][3]);
        }
    }

    // ---- stats over this warp's 32 j-cols ----
    int jb = blockIdx.x * 4 + warp_j;
#pragma unroll
    for (int ti = 0; ti < 4; ti++) {
        float m0 = -1e30f, m1 = -1e30f;
#pragma unroll
        for (int tj = 0; tj < 4; tj++) {
            m0 = fmaxf(m0, fmaxf(cfr[ti][tj][0], cfr[ti][tj][1]));
            m1 = fmaxf(m1, fmaxf(cfr[ti][tj][2], cfr[ti][tj][3]));
        }
#pragma unroll
        for (int o = 1; o < 4; o <<= 1) {
            m0 = fmaxf(m0, __shfl_xor_sync(0xffffffffu, m0, o));
            m1 = fmaxf(m1, __shfl_xor_sync(0xffffffffu, m1, o));
        }
        float s0 = 0.f, s1 = 0.f;
#pragma unroll
        for (int tj = 0; tj < 4; tj++) {
            s0 += __expf(cfr[ti][tj][0] - m0) + __expf(cfr[ti][tj][1] - m0);
            s1 += __expf(cfr[ti][tj][2] - m1) + __expf(cfr[ti][tj][3] - m1);
        }
#pragma unroll
        for (int o = 1; o < 4; o <<= 1) {
            s0 += __shfl_xor_sync(0xffffffffu, s0, o);
            s1 += __shfl_xor_sync(0xffffffffu, s1, o);
        }
        if (ctid == 0) {
            int row = i0 + ibase + ti * 16 + gid;
            size_t sbase = ((size_t)b * JB + jb) * NPOS;
            g_mpart[sbase + row]     = m0;
            g_spart[sbase + row]     = s0;
            g_mpart[sbase + row + 8] = m1;
            g_spart[sbase + row + 8] = s1;
        }
    }
}

// ================= K3: combine stats =================
__global__ void __launch_bounds__(256) combine_kernel()
{
    int e = blockIdx.x * 256 + threadIdx.x;
    if (e >= NB * NPOS) return;
    int b = e / NPOS, i = e % NPOS;
    const float* mp = g_mpart + (size_t)b * JB * NPOS + i;
    const float* sp = g_spart + (size_t)b * JB * NPOS + i;
    float m = -1e30f;
#pragma unroll 8
    for (int jb = 0; jb < JB; jb++) m = fmaxf(m, mp[(size_t)jb * NPOS]);
    float s = 0.f;
#pragma unroll 8
    for (int jb = 0; jb < JB; jb++)
        s += __expf(mp[(size_t)jb * NPOS] - m) * sp[(size_t)jb * NPOS];
    g_m[e] = m;
    g_w[e] = 1.f / s;
}

// ================= K4: agg via mma.sync tf32, exp inline =================
// out[c][j] = sum_i v[c][i] * P[i][j];  M=64 c, N=128 j, K=i chunks of 64.
// grid (32 jt, ASPLIT, NB), block 256 (8 warps: 2 c x 4 j).
#define AG_VS 68
#define AG_PS 132
#define AG_OFF_P (64 * AG_VS)
#define AG_OFF_M (64 * AG_VS + 64 * AG_PS)
#define AG_OFF_W (AG_OFF_M + 64)
#define AG_SMEM  ((AG_OFF_W + 64) * 4)
__global__ void __launch_bounds__(256) agg_kernel()
{
    extern __shared__ float sm[];
    float* sV = sm;                 // [64 c][68]
    float* sP = sm + AG_OFF_P;      // [64 i][132]
    float* sM = sm + AG_OFF_M;
    float* sW = sm + AG_OFF_W;

    int b  = blockIdx.z;
    int ks = blockIdx.y;
    int j0 = blockIdx.x * 128;
    const int IRANGE = NPOS / ASPLIT;       // 512
    int ibase_g = ks * IRANGE;

    int tid = threadIdx.x, wid = tid >> 5, lane = tid & 31;
    int gid = lane >> 2, ctid = lane & 3;
    int warp_c = wid >> 2;                  // 0..1
    int warp_j = wid & 3;                   // 0..3
    int cbase = warp_c * 32, jbase = warp_j * 32;

    const float* vb = g_v + (size_t)b * CH * NPOS;
    const float* Sb = g_S + (size_t)b * NPOS * NPOS;

    float cfr[2][4][4];
#pragma unroll
    for (int ti = 0; ti < 2; ti++)
#pragma unroll
        for (int tj = 0; tj < 4; tj++)
#pragma unroll
            for (int r = 0; r < 4; r++) cfr[ti][tj][r] = 0.f;

#pragma unroll 1
    for (int ck = 0; ck < IRANGE / 64; ck++) {
        int i0 = ibase_g + ck * 64;
        __syncthreads();
        if (tid < 64) {
            sM[tid] = g_m[b * NPOS + i0 + tid];
            sW[tid] = g_w[b * NPOS + i0 + tid];
        }
        // stage V [64 c][64 i]
        for (int idx = tid; idx < 1024; idx += 256) {
            int c = idx >> 4, i4 = (idx & 15) * 4;
            *(float4*)&sV[c * AG_VS + i4] =
                *(const float4*)&vb[(size_t)c * NPOS + i0 + i4];
        }
        __syncthreads();    // sM/sW visible
        // stage P [64 i][128 j] with exp inline: 1024 iters x 8 floats
        for (int idx = tid; idx < 1024; idx += 256) {
            int ii = idx >> 4, jj4 = (idx & 15) * 8;
            float4 s0 = *(const float4*)&Sb[(size_t)(i0 + ii) * NPOS + j0 + jj4];
            float4 s1 = *(const float4*)&Sb[(size_t)(i0 + ii) * NPOS + j0 + jj4 + 4];
            float m = sM[ii], w = sW[ii];
            float4 p0 = make_float4(__expf(s0.x - m) * w, __expf(s0.y - m) * w,
                                    __expf(s0.z - m) * w, __expf(s0.w - m) * w);
            float4 p1 = make_float4(__expf(s1.x - m) * w, __expf(s1.y - m) * w,
                                    __expf(s1.z - m) * w, __expf(s1.w - m) * w);
            *(float4*)&sP[ii * AG_PS + jj4]     = p0;
            *(float4*)&sP[ii * AG_PS + jj4 + 4] = p1;
        }
        __syncthreads();

#pragma unroll
        for (int kk = 0; kk < 8; kk++) {
            int k = kk * 8 + ctid;
            u32 ahi[2][4], alo[2][4];
#pragma unroll
            for (int ti = 0; ti < 2; ti++) {
                const float* v0 = &sV[(cbase + ti * 16 + gid) * AG_VS + k];
                const float* v1 = &sV[(cbase + ti * 16 + gid + 8) * AG_VS + k];
                split32(v0[0], ahi[ti][0], alo[ti][0]);
                split32(v1[0], ahi[ti][1], alo[ti][1]);
                split32(v0[4], ahi[ti][2], alo[ti][2]);
                split32(v1[4], ahi[ti][3], alo[ti][3]);
            }
            u32 bhi[4][2], blo[4][2];
#pragma unroll
            for (int tj = 0; tj < 4; tj++) {
                float p0 = sP[k * AG_PS + jbase + tj * 8 + gid];
                float p1 = sP[(k + 4) * AG_PS + jbase + tj * 8 + gid];
                split32(p0, bhi[tj][0], blo[tj][0]);
                split32(p1, bhi[tj][1], blo[tj][1]);
            }
#pragma unroll
            for (int ti = 0; ti < 2; ti++)
#pragma unroll
                for (int tj = 0; tj < 4; tj++) {
                    mma_tf32(cfr[ti][tj], ahi[ti][0], ahi[ti][1], ahi[ti][2], ahi[ti][3],
                             bhi[tj][0], bhi[tj][1]);
                    mma_tf32(cfr[ti][tj], ahi[ti][0], ahi[ti][1], ahi[ti][2], ahi[ti][3],
                             blo[tj][0], blo[tj][1]);
                    mma_tf32(cfr[ti][tj], alo[ti][0], alo[ti][1], alo[ti][2], alo[ti][3],
                             bhi[tj][0], bhi[tj][1]);
                }
        }
    }

    float* ap = g_aggp[ks] + (size_t)b * CH * NPOS;
#pragma unroll
    for (int ti = 0; ti < 2; ti++) {
        int c0 = cbase + ti * 16 + gid;
#pragma unroll
        for (int tj = 0; tj < 4; tj++) {
            int col = j0 + jbase + tj * 8 + 2 * ctid;
            *(float2*)&ap[(size_t)c0 * NPOS + col] =
                make_float2(cfr[ti][tj][0], cfr[ti][tj][1]);
            *(float2*)&ap[(size_t)(c0 + 8) * NPOS + col] =
                make_float2(cfr[ti][tj][2], cfr[ti][tj][3]);
        }
    }
}

// ================= K4b: reduce split-K partials =================
__global__ void __launch_bounds__(256) agg_reduce_kernel()
{
    int e = blockIdx.x * 256 + threadIdx.x;
    if (e >= NB * CH * NPOS) return;
    float s = 0.f;
#pragma unroll
    for (int ks = 0; ks < ASPLIT; ks++) s += g_aggp[ks][e];
    g_agg[e] = s;
}

// ================= K5: out = Wpost * agg + x =================
__global__ void __launch_bounds__(128) post_kernel(
    const float* __restrict__ x,
    const float* __restrict__ Wpost,
    float* __restrict__ out)
{
    int b   = blockIdx.x;
    int pos = blockIdx.y * 128 + threadIdx.x;
    int o0  = blockIdx.z * 8;

    float acc[8];
#pragma unroll
    for (int u = 0; u < 8; u++) acc[u] = 0.f;
    const float* ap = g_agg + (size_t)b * CH * NPOS + pos;
#pragma unroll 4
    for (int c = 0; c < CH; c++) {
        float av = ap[(size_t)c * NPOS];
#pragma unroll
        for (int u = 0; u < 8; u++)
            acc[u] += Wpost[(o0 + u) * CH + c] * av;
    }
#pragma unroll
    for (int u = 0; u < 8; u++) {
        size_t o = ((size_t)b * CIN + o0 + u) * NPOS + pos;
        out[o] = acc[u] + x[o];
    }
}

// ================= launch =================
extern "C" void kernel_launch(void* const* d_in, const int* in_sizes, int n_in,
                              void* d_out, int out_size)
{
    const float* x     = (const float*)d_in[0];
    const float* Wq    = (const float*)d_in[1];
    const float* Wk    = (const float*)d_in[2];
    const float* Wv    = (const float*)d_in[3];
    const float* Wpost = (const float*)d_in[4];
    float* out = (float*)d_out;

    cudaFuncSetAttribute(scores_kernel, cudaFuncAttributeMaxDynamicSharedMemorySize, SC_SMEM);
    cudaFuncSetAttribute(agg_kernel,    cudaFuncAttributeMaxDynamicSharedMemorySize, AG_SMEM);

    qkv_kernel<<<dim3(NB, NPOS / 128, 24), 128>>>(x, Wq, Wk, Wv);
    scores_kernel<<<dim3(NPOS / 128, NPOS / 128, NB), 256, SC_SMEM>>>();
    combine_kernel<<<(NB * NPOS + 255) / 256, 256>>>();
    agg_kernel<<<dim3(NPOS / 128, ASPLIT, NB), 256, AG_SMEM>>>();
    agg_reduce_kernel<<<(NB * CH * NPOS + 255) / 256, 256>>>();
    post_kernel<<<dim3(NB, NPOS / 128, 16), 128>>>(x, Wpost, out);
}